// round 6
// baseline (speedup 1.0000x reference)
#include <cuda_runtime.h>
#include <math.h>

#define BSZ 2
#define SSZ 2048
#define DSZ 1024
#define HN  16
#define DK  64
#define NPAIR 32

__device__ float g_Q[BSZ*HN*SSZ*DK];
__device__ float g_K[BSZ*HN*SSZ*DK];
__device__ float g_V[BSZ*HN*SSZ*DK];
__device__ float g_O[BSZ*SSZ*DSZ];
__device__ float g_X[BSZ*SSZ*DSZ];     // tf32-rounded x
__device__ float g_Wq[DSZ*DSZ];        // tf32-rounded weights
__device__ float g_Wk[DSZ*DSZ];
__device__ float g_Wv[DSZ*DSZ];
__device__ float g_Wo[DSZ*DSZ];
__device__ float g_cos[SSZ*NPAIR];
__device__ float g_sin[SSZ*NPAIR];

// ---------------------------------------------------------------------------
// helpers
// ---------------------------------------------------------------------------
__device__ __forceinline__ unsigned f2tf(float f) {
    unsigned u;
    asm("cvt.rna.tf32.f32 %0, %1;" : "=r"(u) : "f"(f));
    return u;
}
__device__ __forceinline__ float f2tff(float f) { return __uint_as_float(f2tf(f)); }

__device__ __forceinline__ void mma8(float* c, const unsigned* a, const unsigned* b) {
    asm volatile(
        "mma.sync.aligned.m16n8k8.row.col.f32.tf32.tf32.f32 "
        "{%0,%1,%2,%3}, {%4,%5,%6,%7}, {%8,%9}, {%0,%1,%2,%3};"
        : "+f"(c[0]), "+f"(c[1]), "+f"(c[2]), "+f"(c[3])
        : "r"(a[0]), "r"(a[1]), "r"(a[2]), "r"(a[3]), "r"(b[0]), "r"(b[1]));
}

__device__ __forceinline__ void cpa16(float* s, const float* g) {
    unsigned sa = (unsigned)__cvta_generic_to_shared(s);
    asm volatile("cp.async.cg.shared.global [%0], [%1], 16;" :: "r"(sa), "l"(g));
}
__device__ __forceinline__ void cpa_commit() {
    asm volatile("cp.async.commit_group;");
}
template <int N>
__device__ __forceinline__ void cpa_wait() {
    asm volatile("cp.async.wait_group %0;" :: "n"(N));
}

// ---------------------------------------------------------------------------
// tf32 pre-round pass
// ---------------------------------------------------------------------------
__global__ void tf32_round_kernel(const float4* __restrict__ src,
                                  float4* __restrict__ dst, int n4) {
    int i = blockIdx.x * blockDim.x + threadIdx.x;
    if (i >= n4) return;
    float4 v = src[i];
    float4 o;
    o.x = f2tff(v.x); o.y = f2tff(v.y); o.z = f2tff(v.z); o.w = f2tff(v.w);
    dst[i] = o;
}

// ---------------------------------------------------------------------------
// RoPE table
// ---------------------------------------------------------------------------
__global__ void rope_table_kernel() {
    int i = blockIdx.x * blockDim.x + threadIdx.x;
    if (i >= SSZ * NPAIR) return;
    int s = i >> 5, p = i & 31;
    double ang = (double)s * exp(-(double)p * (9.210340371976184 / 32.0));
    g_cos[i] = (float)cos(ang);
    g_sin[i] = (float)sin(ang);
}

// ---------------------------------------------------------------------------
// tf32 NT-GEMM: C[128x128] = A[128x1024] * W[128x1024]^T
// 128 thr / 4 warps in 2x2, warp tile 64x64, BK=16, 4-stage cp.async.
// Inputs pre-rounded. Both k-steps' fragments batched for max LDS MLP.
// ---------------------------------------------------------------------------
#define GST 20
#define GSTG 4
#define GBUF (128*GST)

struct GemmCtx { int g, t, wm, wn; };

__device__ __forceinline__ void gemm_issue(
    float* As, float* Bs, int st,
    const float* __restrict__ A, const float* __restrict__ W,
    int m0, int n0, int kb)
{
    float* as = As + st * GBUF;
    float* bs = Bs + st * GBUF;
    const int r0 = threadIdx.x >> 2;
    const int c4 = (threadIdx.x & 3) << 2;
#pragma unroll
    for (int i = 0; i < 4; i++) {
        int r = r0 + 32 * i;
        cpa16(&as[r * GST + c4], A + (size_t)(m0 + r) * 1024 + kb + c4);
        cpa16(&bs[r * GST + c4], W + (size_t)(n0 + r) * 1024 + kb + c4);
    }
}

__device__ __forceinline__ void gemm_comp(
    const float* As, const float* Bs, int st,
    float (&acc)[4][8][4], const GemmCtx& cx)
{
    const float* as = As + st * GBUF;
    const float* bs = Bs + st * GBUF;
    unsigned af[2][4][4], bf[2][8][2];
    // batch ALL fragment loads (64 LDS.32, fully independent)
#pragma unroll
    for (int ks = 0; ks < 2; ks++) {
        const int k0 = ks * 8;
#pragma unroll
        for (int mt = 0; mt < 4; mt++) {
            const float* p = as + (cx.wm + mt*16 + cx.g) * GST + k0 + cx.t;
            af[ks][mt][0] = __float_as_uint(p[0]);
            af[ks][mt][1] = __float_as_uint(p[8*GST]);
            af[ks][mt][2] = __float_as_uint(p[4]);
            af[ks][mt][3] = __float_as_uint(p[8*GST + 4]);
        }
#pragma unroll
        for (int nt = 0; nt < 8; nt++) {
            const float* p = bs + (cx.wn + nt*8 + cx.g) * GST + k0 + cx.t;
            bf[ks][nt][0] = __float_as_uint(p[0]);
            bf[ks][nt][1] = __float_as_uint(p[4]);
        }
    }
    // then a long independent mma stream
#pragma unroll
    for (int ks = 0; ks < 2; ks++)
#pragma unroll
        for (int nt = 0; nt < 8; nt++)
#pragma unroll
            for (int mt = 0; mt < 4; mt++)
                mma8(acc[mt][nt], af[ks][mt], bf[ks][nt]);
}

__device__ __forceinline__ void gemm_main(
    const float* __restrict__ A, const float* __restrict__ W,
    int m0, int n0, float (&acc)[4][8][4],
    float* As, float* Bs, const GemmCtx& cx)
{
#pragma unroll
    for (int s = 0; s < GSTG - 1; s++) {
        gemm_issue(As, Bs, s, A, W, m0, n0, s * 16);
        cpa_commit();
    }
    for (int kb = 0; kb < 64; kb++) {
        cpa_wait<GSTG - 2>();
        __syncthreads();
        if (kb + GSTG - 1 < 64)
            gemm_issue(As, Bs, (kb + GSTG - 1) % GSTG, A, W, m0, n0, (kb + GSTG - 1) * 16);
        cpa_commit();
        gemm_comp(As, Bs, kb % GSTG, acc, cx);
    }
}

// QKV projection with fused RoPE, scattered to [B,H,S,dk], tf32-rounded output
__global__ __launch_bounds__(128) void gemm_qkv_kernel()
{
    extern __shared__ float sm[];
    float* As = sm;
    float* Bs = sm + GSTG * GBUF;

    const int z = blockIdx.z;
    const float* W = z == 0 ? g_Wq : (z == 1 ? g_Wk : g_Wv);
    float* dst     = z == 0 ? g_Q  : (z == 1 ? g_K  : g_V);

    const int lane = threadIdx.x & 31;
    const int wid = threadIdx.x >> 5;
    GemmCtx cx;
    cx.g = lane >> 2; cx.t = lane & 3;
    cx.wm = (wid & 1) * 64; cx.wn = (wid >> 1) * 64;
    const int m0 = blockIdx.y * 128, n0 = blockIdx.x * 128;

    float acc[4][8][4];
#pragma unroll
    for (int i = 0; i < 4; i++)
#pragma unroll
        for (int j = 0; j < 8; j++)
#pragma unroll
            for (int k = 0; k < 4; k++) acc[i][j][k] = 0.f;

    gemm_main(g_X, W, m0, n0, acc, As, Bs, cx);

    const bool do_rope = (z < 2);
#pragma unroll
    for (int mt = 0; mt < 4; mt++) {
        int m = m0 + cx.wm + mt * 16 + cx.g;
        int b = m >> 11, s = m & (SSZ - 1);
#pragma unroll
        for (int nt = 0; nt < 8; nt++) {
            int n = n0 + cx.wn + nt * 8 + 2 * cx.t;
            int h = n >> 6, c = n & 63;
            float v0 = acc[mt][nt][0], v1 = acc[mt][nt][1];
            float v2 = acc[mt][nt][2], v3 = acc[mt][nt][3];
            if (do_rope) {
                int p = c >> 1;
                float ca0 = g_cos[(s << 5) | p],       sa0 = g_sin[(s << 5) | p];
                float ca1 = g_cos[((s + 8) << 5) | p], sa1 = g_sin[((s + 8) << 5) | p];
                float r0 = v0 * ca0 - v1 * sa0;
                float r1 = v0 * sa0 + v1 * ca0;
                float r2 = v2 * ca1 - v3 * sa1;
                float r3 = v2 * sa1 + v3 * ca1;
                v0 = r0; v1 = r1; v2 = r2; v3 = r3;
            }
            v0 = f2tff(v0); v1 = f2tff(v1); v2 = f2tff(v2); v3 = f2tff(v3);
            float* base = dst + (((size_t)b * HN + h) * SSZ) * DK + c;
            *(float2*)(base + (size_t)s * DK)       = make_float2(v0, v1);
            *(float2*)(base + (size_t)(s + 8) * DK) = make_float2(v2, v3);
        }
    }
}

// Output projection: out = g_O @ g_Wo^T (both pre-rounded)
__global__ __launch_bounds__(128) void gemm_out_kernel(float* __restrict__ C)
{
    extern __shared__ float sm[];
    float* As = sm;
    float* Bs = sm + GSTG * GBUF;

    const int lane = threadIdx.x & 31;
    const int wid = threadIdx.x >> 5;
    GemmCtx cx;
    cx.g = lane >> 2; cx.t = lane & 3;
    cx.wm = (wid & 1) * 64; cx.wn = (wid >> 1) * 64;
    const int m0 = blockIdx.y * 128, n0 = blockIdx.x * 128;

    float acc[4][8][4];
#pragma unroll
    for (int i = 0; i < 4; i++)
#pragma unroll
        for (int j = 0; j < 8; j++)
#pragma unroll
            for (int k = 0; k < 4; k++) acc[i][j][k] = 0.f;

    gemm_main(g_O, g_Wo, m0, n0, acc, As, Bs, cx);

#pragma unroll
    for (int mt = 0; mt < 4; mt++) {
        int m = m0 + cx.wm + mt * 16 + cx.g;
#pragma unroll
        for (int nt = 0; nt < 8; nt++) {
            int n = n0 + cx.wn + nt * 8 + 2 * cx.t;
            *(float2*)(C + (size_t)m * 1024 + n)       = make_float2(acc[mt][nt][0], acc[mt][nt][1]);
            *(float2*)(C + (size_t)(m + 8) * 1024 + n) = make_float2(acc[mt][nt][2], acc[mt][nt][3]);
        }
    }
}

// ---------------------------------------------------------------------------
// tf32 flash attention: 128 thr / 4 warps, BQ=128, BK=64, dk=64.
// Q/K/V pre-rounded. PV phase register-double-buffers pf/vf fragments.
// smem: sQP[128][76] (Q tf32 then P tf32), sK[2][64][68], sV[2][64][72].
// ---------------------------------------------------------------------------
#define SQ_ST 76
#define SK_ST 68
#define SV_ST 72
#define SK_BUF (64*SK_ST)
#define SV_BUF (64*SV_ST)

__global__ __launch_bounds__(128) void attn_kernel() {
    extern __shared__ float sm[];
    float* sQP = sm;                               // 128*76
    float* sK0 = sm + 128*SQ_ST;                   // 2 x 64*68
    float* sV0 = sm + 128*SQ_ST + 2*SK_BUF;        // 2 x 64*72

    const int tid = threadIdx.x;
    const int w = tid >> 5;
    const int lane = tid & 31;
    const int g = lane >> 2, t = lane & 3;
    const int qb = (int)gridDim.x - 1 - (int)blockIdx.x;   // heavy CTAs first
    const int bh = blockIdx.y;
    const float* Qg = g_Q + (size_t)bh * SSZ * DK;
    const float* Kg = g_K + (size_t)bh * SSZ * DK;
    const float* Vg = g_V + (size_t)bh * SSZ * DK;
    const int kb_max = 2 * qb + 1;

    // prologue: issue K/V block 0 loads
#pragma unroll
    for (int i = 0; i < 8; i++) {
        int e = i * 128 + tid;
        int r = e >> 4, c = (e & 15) << 2;
        cpa16(&sK0[r * SK_ST + c], &Kg[(size_t)r * DK + c]);
        cpa16(&sV0[r * SV_ST + c], &Vg[(size_t)r * DK + c]);
    }
    cpa_commit();

    // stage Q: pre-rounded; x0.125 is an exact exponent shift so still tf32
#pragma unroll
    for (int i = 0; i < 16; i++) {
        int e = i * 128 + tid;
        int r = e >> 4, c = (e & 15) << 2;
        float4 v = *(const float4*)&Qg[(size_t)(qb * 128 + r) * DK + c];
        float4 o;
        o.x = v.x * 0.125f; o.y = v.y * 0.125f;
        o.z = v.z * 0.125f; o.w = v.w * 0.125f;
        *(float4*)&sQP[r * SQ_ST + c] = o;
    }
    __syncthreads();

    // hoist Q fragments: 2 m-tiles x 8 k-steps x 4 regs
    unsigned qf[2][8][4];
#pragma unroll
    for (int mt = 0; mt < 2; mt++) {
        const int qr = w * 32 + mt * 16 + g;
#pragma unroll
        for (int ks = 0; ks < 8; ks++) {
            const float* p = &sQP[qr * SQ_ST + ks * 8 + t];
            qf[mt][ks][0] = __float_as_uint(p[0]);
            qf[mt][ks][1] = __float_as_uint(p[8 * SQ_ST]);
            qf[mt][ks][2] = __float_as_uint(p[4]);
            qf[mt][ks][3] = __float_as_uint(p[8 * SQ_ST + 4]);
        }
    }

    float mrun[2][2] = {{-1e30f, -1e30f}, {-1e30f, -1e30f}};
    float lrun[2][2] = {{0.f, 0.f}, {0.f, 0.f}};
    float oacc[2][8][4];
#pragma unroll
    for (int mt = 0; mt < 2; mt++)
#pragma unroll
        for (int nt = 0; nt < 8; nt++)
#pragma unroll
            for (int k = 0; k < 4; k++) oacc[mt][nt][k] = 0.f;

    for (int kb = 0; kb <= kb_max; kb++) {
        __syncthreads();   // buffer (kb+1)&1 free; Q->qf hoist done (kb=0)
        if (kb < kb_max) {
            float* sK = sK0 + ((kb + 1) & 1) * SK_BUF;
            float* sV = sV0 + ((kb + 1) & 1) * SV_BUF;
#pragma unroll
            for (int i = 0; i < 8; i++) {
                int e = i * 128 + tid;
                int r = e >> 4, c = (e & 15) << 2;
                cpa16(&sK[r * SK_ST + c], &Kg[(size_t)((kb + 1) * 64 + r) * DK + c]);
                cpa16(&sV[r * SV_ST + c], &Vg[(size_t)((kb + 1) * 64 + r) * DK + c]);
            }
        }
        cpa_commit();
        cpa_wait<1>();
        __syncthreads();

        const float* sK = sK0 + (kb & 1) * SK_BUF;
        const float* sV = sV0 + (kb & 1) * SV_BUF;

        // S = Q K^T : batch kf loads per k-step, then mma
        float s[2][8][4];
#pragma unroll
        for (int mt = 0; mt < 2; mt++)
#pragma unroll
            for (int nt = 0; nt < 8; nt++)
#pragma unroll
                for (int k = 0; k < 4; k++) s[mt][nt][k] = 0.f;

#pragma unroll
        for (int ks = 0; ks < 8; ks++) {
            unsigned kf[8][2];
#pragma unroll
            for (int nt = 0; nt < 8; nt++) {
                const float* p = &sK[(nt * 8 + g) * SK_ST + ks * 8 + t];
                kf[nt][0] = __float_as_uint(p[0]);
                kf[nt][1] = __float_as_uint(p[4]);
            }
#pragma unroll
            for (int nt = 0; nt < 8; nt++) {
                mma8(s[0][nt], qf[0][ks], kf[nt]);
                mma8(s[1][nt], qf[1][ks], kf[nt]);
            }
        }

        // causal mask (only the last two kv-blocks intersect the diagonal)
        if (kb >= 2 * qb) {
#pragma unroll
            for (int mt = 0; mt < 2; mt++) {
                int qg = qb * 128 + w * 32 + mt * 16 + g;
#pragma unroll
                for (int nt = 0; nt < 8; nt++) {
                    int col = kb * 64 + nt * 8 + 2 * t;
                    if (col     > qg)     s[mt][nt][0] = -1e30f;
                    if (col + 1 > qg)     s[mt][nt][1] = -1e30f;
                    if (col     > qg + 8) s[mt][nt][2] = -1e30f;
                    if (col + 1 > qg + 8) s[mt][nt][3] = -1e30f;
                }
            }
        }

        __syncwarp();   // this warp's prior PV reads of its P rows done

        // online softmax per m-tile, per row-half
#pragma unroll
        for (int mt = 0; mt < 2; mt++) {
            const int qr = w * 32 + mt * 16 + g;
#pragma unroll
            for (int r = 0; r < 2; r++) {
                float mx = -1e30f;
#pragma unroll
                for (int nt = 0; nt < 8; nt++)
                    mx = fmaxf(mx, fmaxf(s[mt][nt][2*r], s[mt][nt][2*r + 1]));
                mx = fmaxf(mx, __shfl_xor_sync(0xffffffffu, mx, 1));
                mx = fmaxf(mx, __shfl_xor_sync(0xffffffffu, mx, 2));
                float mnew = fmaxf(mrun[mt][r], mx);
                float corr = __expf(mrun[mt][r] - mnew);
                float rs = 0.f;
                float* prow = &sQP[(qr + 8 * r) * SQ_ST];
#pragma unroll
                for (int nt = 0; nt < 8; nt++) {
                    float p0 = __expf(s[mt][nt][2*r]     - mnew);
                    float p1 = __expf(s[mt][nt][2*r + 1] - mnew);
                    rs += p0 + p1;
                    *(float2*)&prow[nt * 8 + 2 * t] = make_float2(f2tff(p0), f2tff(p1));
                }
                rs += __shfl_xor_sync(0xffffffffu, rs, 1);
                rs += __shfl_xor_sync(0xffffffffu, rs, 2);
                lrun[mt][r] = lrun[mt][r] * corr + rs;
                mrun[mt][r] = mnew;
#pragma unroll
                for (int nt = 0; nt < 8; nt++) {
                    oacc[mt][nt][2*r]     *= corr;
                    oacc[mt][nt][2*r + 1] *= corr;
                }
            }
        }
        __syncwarp();

        // O += P V : register double-buffer pf/vf one k-step ahead
        unsigned pf[2][2][4], vf[2][8][2];
        {
            const int ks = 0;
#pragma unroll
            for (int mt = 0; mt < 2; mt++) {
                const float* pp = &sQP[(w * 32 + mt * 16 + g) * SQ_ST + ks * 8 + t];
                pf[0][mt][0] = __float_as_uint(pp[0]);
                pf[0][mt][1] = __float_as_uint(pp[8 * SQ_ST]);
                pf[0][mt][2] = __float_as_uint(pp[4]);
                pf[0][mt][3] = __float_as_uint(pp[8 * SQ_ST + 4]);
            }
#pragma unroll
            for (int nt = 0; nt < 8; nt++) {
                const float* vp = &sV[(ks * 8 + t) * SV_ST + nt * 8 + g];
                vf[0][nt][0] = __float_as_uint(vp[0]);
                vf[0][nt][1] = __float_as_uint(vp[4 * SV_ST]);
            }
        }
#pragma unroll
        for (int ks = 0; ks < 8; ks++) {
            const int cur = ks & 1, nxt = cur ^ 1;
            if (ks < 7) {
                const int kn = ks + 1;
#pragma unroll
                for (int mt = 0; mt < 2; mt++) {
                    const float* pp = &sQP[(w * 32 + mt * 16 + g) * SQ_ST + kn * 8 + t];
                    pf[nxt][mt][0] = __float_as_uint(pp[0]);
                    pf[nxt][mt][1] = __float_as_uint(pp[8 * SQ_ST]);
                    pf[nxt][mt][2] = __float_as_uint(pp[4]);
                    pf[nxt][mt][3] = __float_as_uint(pp[8 * SQ_ST + 4]);
                }
#pragma unroll
                for (int nt = 0; nt < 8; nt++) {
                    const float* vp = &sV[(kn * 8 + t) * SV_ST + nt * 8 + g];
                    vf[nxt][nt][0] = __float_as_uint(vp[0]);
                    vf[nxt][nt][1] = __float_as_uint(vp[4 * SV_ST]);
                }
            }
#pragma unroll
            for (int nt = 0; nt < 8; nt++) {
                mma8(oacc[0][nt], pf[cur][0], vf[cur][nt]);
                mma8(oacc[1][nt], pf[cur][1], vf[cur][nt]);
            }
        }
    }

    // epilogue: normalize, round to tf32, scatter to [B,S,D]
    const int b = bh >> 4;
    const int h = bh & 15;
#pragma unroll
    for (int mt = 0; mt < 2; mt++) {
#pragma unroll
        for (int r = 0; r < 2; r++) {
            float inv = 1.f / lrun[mt][r];
            int q = qb * 128 + w * 32 + mt * 16 + g + 8 * r;
            float* dst = &g_O[((size_t)b * SSZ + q) * DSZ + h * DK];
#pragma unroll
            for (int nt = 0; nt < 8; nt++)
                *(float2*)&dst[nt * 8 + 2 * t] =
                    make_float2(f2tff(oacc[mt][nt][2*r] * inv),
                                f2tff(oacc[mt][nt][2*r + 1] * inv));
        }
    }
}

// ---------------------------------------------------------------------------
extern "C" void kernel_launch(void* const* d_in, const int* in_sizes, int n_in,
                              void* d_out, int out_size) {
    (void)in_sizes; (void)n_in; (void)out_size;
    const float* x  = (const float*)d_in[0];
    const float* Wq = (const float*)d_in[1];
    const float* Wk = (const float*)d_in[2];
    const float* Wv = (const float*)d_in[3];
    const float* Wo = (const float*)d_in[4];
    float* out = (float*)d_out;

    float* gX;  cudaGetSymbolAddress((void**)&gX,  g_X);
    float* gWq; cudaGetSymbolAddress((void**)&gWq, g_Wq);
    float* gWk; cudaGetSymbolAddress((void**)&gWk, g_Wk);
    float* gWv; cudaGetSymbolAddress((void**)&gWv, g_Wv);
    float* gWo; cudaGetSymbolAddress((void**)&gWo, g_Wo);

    const int gemm_smem = 2 * GSTG * GBUF * (int)sizeof(float);  // 81920 B
    cudaFuncSetAttribute(gemm_qkv_kernel, cudaFuncAttributeMaxDynamicSharedMemorySize, gemm_smem);
    cudaFuncSetAttribute(gemm_out_kernel, cudaFuncAttributeMaxDynamicSharedMemorySize, gemm_smem);
    const int attn_smem = (128*SQ_ST + 2*SK_BUF + 2*SV_BUF) * (int)sizeof(float);  // 110592 B
    cudaFuncSetAttribute(attn_kernel, cudaFuncAttributeMaxDynamicSharedMemorySize, attn_smem);

    rope_table_kernel<<<(SSZ * NPAIR + 255) / 256, 256>>>();

    const int NX4 = BSZ*SSZ*DSZ/4, NW4 = DSZ*DSZ/4;
    tf32_round_kernel<<<(NX4 + 255)/256, 256>>>((const float4*)x,  (float4*)gX,  NX4);
    tf32_round_kernel<<<(NW4 + 255)/256, 256>>>((const float4*)Wq, (float4*)gWq, NW4);
    tf32_round_kernel<<<(NW4 + 255)/256, 256>>>((const float4*)Wk, (float4*)gWk, NW4);
    tf32_round_kernel<<<(NW4 + 255)/256, 256>>>((const float4*)Wv, (float4*)gWv, NW4);
    tf32_round_kernel<<<(NW4 + 255)/256, 256>>>((const float4*)Wo, (float4*)gWo, NW4);

    gemm_qkv_kernel<<<dim3(8, 32, 3), 128, gemm_smem>>>();
    attn_kernel<<<dim3(SSZ / 128, BSZ * HN), 128, attn_smem>>>();
    gemm_out_kernel<<<dim3(8, 32), 128, gemm_smem>>>(out);
}

// round 7
// speedup vs baseline: 1.1283x; 1.1283x over previous
#include <cuda_runtime.h>
#include <math.h>

#define BSZ 2
#define SSZ 2048
#define DSZ 1024
#define HN  16
#define DK  64
#define NPAIR 32

__device__ float g_Q[BSZ*HN*SSZ*DK];
__device__ float g_K[BSZ*HN*SSZ*DK];
__device__ float g_V[BSZ*HN*SSZ*DK];
__device__ float g_O[BSZ*SSZ*DSZ];
__device__ float g_X[BSZ*SSZ*DSZ];     // tf32-rounded x
__device__ float g_Wq[DSZ*DSZ];        // tf32-rounded weights
__device__ float g_Wk[DSZ*DSZ];
__device__ float g_Wv[DSZ*DSZ];
__device__ float g_Wo[DSZ*DSZ];
__device__ float g_cos[SSZ*NPAIR];
__device__ float g_sin[SSZ*NPAIR];

// ---------------------------------------------------------------------------
// helpers
// ---------------------------------------------------------------------------
__device__ __forceinline__ unsigned f2tf(float f) {
    unsigned u;
    asm("cvt.rna.tf32.f32 %0, %1;" : "=r"(u) : "f"(f));
    return u;
}
__device__ __forceinline__ float f2tff(float f) { return __uint_as_float(f2tf(f)); }

__device__ __forceinline__ void mma8(float* c, const unsigned* a, const unsigned* b) {
    asm volatile(
        "mma.sync.aligned.m16n8k8.row.col.f32.tf32.tf32.f32 "
        "{%0,%1,%2,%3}, {%4,%5,%6,%7}, {%8,%9}, {%0,%1,%2,%3};"
        : "+f"(c[0]), "+f"(c[1]), "+f"(c[2]), "+f"(c[3])
        : "r"(a[0]), "r"(a[1]), "r"(a[2]), "r"(a[3]), "r"(b[0]), "r"(b[1]));
}

__device__ __forceinline__ void cpa16(float* s, const float* g) {
    unsigned sa = (unsigned)__cvta_generic_to_shared(s);
    asm volatile("cp.async.cg.shared.global [%0], [%1], 16;" :: "r"(sa), "l"(g));
}
__device__ __forceinline__ void cpa_commit() {
    asm volatile("cp.async.commit_group;");
}
template <int N>
__device__ __forceinline__ void cpa_wait() {
    asm volatile("cp.async.wait_group %0;" :: "n"(N));
}

// ---------------------------------------------------------------------------
// Merged tf32 pre-round pass: x + 4 weight matrices in one launch
// ---------------------------------------------------------------------------
#define NX4 (BSZ*SSZ*DSZ/4)
#define NW4 (DSZ*DSZ/4)

__global__ void tf32_round_all_kernel(const float4* __restrict__ x,
                                      const float4* __restrict__ wq,
                                      const float4* __restrict__ wk,
                                      const float4* __restrict__ wv,
                                      const float4* __restrict__ wo) {
    int i = blockIdx.x * blockDim.x + threadIdx.x;
    const float4* src;
    float4* dst;
    if (i < NX4) {
        src = x + i;
        dst = (float4*)g_X + i;
    } else {
        int j = i - NX4;
        int wsel = j / NW4;
        int off = j - wsel * NW4;
        src = (wsel == 0 ? wq : wsel == 1 ? wk : wsel == 2 ? wv : wo) + off;
        dst = (float4*)(wsel == 0 ? g_Wq : wsel == 1 ? g_Wk : wsel == 2 ? g_Wv : g_Wo) + off;
    }
    float4 v = *src;
    float4 o;
    o.x = f2tff(v.x); o.y = f2tff(v.y); o.z = f2tff(v.z); o.w = f2tff(v.w);
    *dst = o;
}

// ---------------------------------------------------------------------------
// RoPE table
// ---------------------------------------------------------------------------
__global__ void rope_table_kernel() {
    int i = blockIdx.x * blockDim.x + threadIdx.x;
    if (i >= SSZ * NPAIR) return;
    int s = i >> 5, p = i & 31;
    double ang = (double)s * exp(-(double)p * (9.210340371976184 / 32.0));
    g_cos[i] = (float)cos(ang);
    g_sin[i] = (float)sin(ang);
}

// ---------------------------------------------------------------------------
// tf32 NT-GEMM: C[128x128] = A[128x1024] * W[128x1024]^T
// 128 thr / 4 warps in 2x2, warp tile 64x64, BK=32 stages, 3-stage cp.async,
// fragment double-buffer across the 4 k-steps in a stage.
// smem row stride 36: (36g+t)&31 = 4g+t -> conflict-free fragment LDS.
// ---------------------------------------------------------------------------
#define GST 36
#define GSTG 3
#define GBUF (128*GST)
#define NKT 32          // 1024 / 32 k-tiles

struct GemmCtx { int g, t, wm, wn; };

__device__ __forceinline__ void gemm_issue(
    float* As, float* Bs, int st,
    const float* __restrict__ A, const float* __restrict__ W,
    int m0, int n0, int kb)
{
    float* as = As + st * GBUF;
    float* bs = Bs + st * GBUF;
    const int r0 = threadIdx.x >> 3;        // 0..15
    const int c4 = (threadIdx.x & 7) << 2;  // 0,4,...,28
#pragma unroll
    for (int i = 0; i < 8; i++) {
        int r = r0 + 16 * i;
        cpa16(&as[r * GST + c4], A + (size_t)(m0 + r) * 1024 + kb + c4);
        cpa16(&bs[r * GST + c4], W + (size_t)(n0 + r) * 1024 + kb + c4);
    }
}

__device__ __forceinline__ void gemm_ldfrag(
    const float* as, const float* bs, int ks,
    unsigned (&af)[4][4], unsigned (&bf)[8][2], const GemmCtx& cx)
{
    const int k0 = ks * 8;
#pragma unroll
    for (int mt = 0; mt < 4; mt++) {
        const float* p = as + (cx.wm + mt*16 + cx.g) * GST + k0 + cx.t;
        af[mt][0] = __float_as_uint(p[0]);
        af[mt][1] = __float_as_uint(p[8*GST]);
        af[mt][2] = __float_as_uint(p[4]);
        af[mt][3] = __float_as_uint(p[8*GST + 4]);
    }
#pragma unroll
    for (int nt = 0; nt < 8; nt++) {
        const float* p = bs + (cx.wn + nt*8 + cx.g) * GST + k0 + cx.t;
        bf[nt][0] = __float_as_uint(p[0]);
        bf[nt][1] = __float_as_uint(p[4]);
    }
}

__device__ __forceinline__ void gemm_main(
    const float* __restrict__ A, const float* __restrict__ W,
    int m0, int n0, float (&acc)[4][8][4],
    float* As, float* Bs, const GemmCtx& cx)
{
#pragma unroll
    for (int s = 0; s < GSTG - 1; s++) {
        gemm_issue(As, Bs, s, A, W, m0, n0, s * 32);
        cpa_commit();
    }
    unsigned af[2][4][4], bf[2][8][2];
    for (int kb = 0; kb < NKT; kb++) {
        cpa_wait<GSTG - 2>();
        __syncthreads();
        if (kb + GSTG - 1 < NKT)
            gemm_issue(As, Bs, (kb + GSTG - 1) % GSTG, A, W, m0, n0, (kb + GSTG - 1) * 32);
        cpa_commit();

        const float* as = As + (kb % GSTG) * GBUF;
        const float* bs = Bs + (kb % GSTG) * GBUF;
        gemm_ldfrag(as, bs, 0, af[0], bf[0], cx);
#pragma unroll
        for (int ks = 0; ks < 4; ks++) {
            const int cur = ks & 1;
            if (ks < 3)
                gemm_ldfrag(as, bs, ks + 1, af[cur ^ 1], bf[cur ^ 1], cx);
#pragma unroll
            for (int nt = 0; nt < 8; nt++)
#pragma unroll
                for (int mt = 0; mt < 4; mt++)
                    mma8(acc[mt][nt], af[cur][mt], bf[cur][nt]);
        }
    }
}

// QKV projection with fused RoPE, scattered to [B,H,S,dk], tf32-rounded output
__global__ __launch_bounds__(128) void gemm_qkv_kernel()
{
    extern __shared__ float sm[];
    float* As = sm;
    float* Bs = sm + GSTG * GBUF;

    const int z = blockIdx.z;
    const float* W = z == 0 ? g_Wq : (z == 1 ? g_Wk : g_Wv);
    float* dst     = z == 0 ? g_Q  : (z == 1 ? g_K  : g_V);

    const int lane = threadIdx.x & 31;
    const int wid = threadIdx.x >> 5;
    GemmCtx cx;
    cx.g = lane >> 2; cx.t = lane & 3;
    cx.wm = (wid & 1) * 64; cx.wn = (wid >> 1) * 64;
    const int m0 = blockIdx.y * 128, n0 = blockIdx.x * 128;

    float acc[4][8][4];
#pragma unroll
    for (int i = 0; i < 4; i++)
#pragma unroll
        for (int j = 0; j < 8; j++)
#pragma unroll
            for (int k = 0; k < 4; k++) acc[i][j][k] = 0.f;

    gemm_main(g_X, W, m0, n0, acc, As, Bs, cx);

    const bool do_rope = (z < 2);
#pragma unroll
    for (int mt = 0; mt < 4; mt++) {
        int m = m0 + cx.wm + mt * 16 + cx.g;
        int b = m >> 11, s = m & (SSZ - 1);
#pragma unroll
        for (int nt = 0; nt < 8; nt++) {
            int n = n0 + cx.wn + nt * 8 + 2 * cx.t;
            int h = n >> 6, c = n & 63;
            float v0 = acc[mt][nt][0], v1 = acc[mt][nt][1];
            float v2 = acc[mt][nt][2], v3 = acc[mt][nt][3];
            if (do_rope) {
                int p = c >> 1;
                float ca0 = g_cos[(s << 5) | p],       sa0 = g_sin[(s << 5) | p];
                float ca1 = g_cos[((s + 8) << 5) | p], sa1 = g_sin[((s + 8) << 5) | p];
                float r0 = v0 * ca0 - v1 * sa0;
                float r1 = v0 * sa0 + v1 * ca0;
                float r2 = v2 * ca1 - v3 * sa1;
                float r3 = v2 * sa1 + v3 * ca1;
                v0 = r0; v1 = r1; v2 = r2; v3 = r3;
            }
            v0 = f2tff(v0); v1 = f2tff(v1); v2 = f2tff(v2); v3 = f2tff(v3);
            float* base = dst + (((size_t)b * HN + h) * SSZ) * DK + c;
            *(float2*)(base + (size_t)s * DK)       = make_float2(v0, v1);
            *(float2*)(base + (size_t)(s + 8) * DK) = make_float2(v2, v3);
        }
    }
}

// Output projection: out = g_O @ g_Wo^T (both pre-rounded)
__global__ __launch_bounds__(128) void gemm_out_kernel(float* __restrict__ C)
{
    extern __shared__ float sm[];
    float* As = sm;
    float* Bs = sm + GSTG * GBUF;

    const int lane = threadIdx.x & 31;
    const int wid = threadIdx.x >> 5;
    GemmCtx cx;
    cx.g = lane >> 2; cx.t = lane & 3;
    cx.wm = (wid & 1) * 64; cx.wn = (wid >> 1) * 64;
    const int m0 = blockIdx.y * 128, n0 = blockIdx.x * 128;

    float acc[4][8][4];
#pragma unroll
    for (int i = 0; i < 4; i++)
#pragma unroll
        for (int j = 0; j < 8; j++)
#pragma unroll
            for (int k = 0; k < 4; k++) acc[i][j][k] = 0.f;

    gemm_main(g_O, g_Wo, m0, n0, acc, As, Bs, cx);

#pragma unroll
    for (int mt = 0; mt < 4; mt++) {
        int m = m0 + cx.wm + mt * 16 + cx.g;
#pragma unroll
        for (int nt = 0; nt < 8; nt++) {
            int n = n0 + cx.wn + nt * 8 + 2 * cx.t;
            *(float2*)(C + (size_t)m * 1024 + n)       = make_float2(acc[mt][nt][0], acc[mt][nt][1]);
            *(float2*)(C + (size_t)(m + 8) * 1024 + n) = make_float2(acc[mt][nt][2], acc[mt][nt][3]);
        }
    }
}

// ---------------------------------------------------------------------------
// tf32 flash attention (exact R5 structure): 128 thr / 4 warps, BQ=128, BK=64.
// smem: sQP[128][76] (Q tf32 then P tf32), sK[2][64][68], sV[2][64][72].
// ---------------------------------------------------------------------------
#define SQ_ST 76
#define SK_ST 68
#define SV_ST 72
#define SK_BUF (64*SK_ST)
#define SV_BUF (64*SV_ST)

__global__ __launch_bounds__(128) void attn_kernel() {
    extern __shared__ float sm[];
    float* sQP = sm;                               // 128*76
    float* sK0 = sm + 128*SQ_ST;                   // 2 x 64*68
    float* sV0 = sm + 128*SQ_ST + 2*SK_BUF;        // 2 x 64*72

    const int tid = threadIdx.x;
    const int w = tid >> 5;
    const int lane = tid & 31;
    const int g = lane >> 2, t = lane & 3;
    const int qb = (int)gridDim.x - 1 - (int)blockIdx.x;   // heavy CTAs first
    const int bh = blockIdx.y;
    const float* Qg = g_Q + (size_t)bh * SSZ * DK;
    const float* Kg = g_K + (size_t)bh * SSZ * DK;
    const float* Vg = g_V + (size_t)bh * SSZ * DK;
    const int kb_max = 2 * qb + 1;

    // prologue: issue K/V block 0 loads
#pragma unroll
    for (int i = 0; i < 8; i++) {
        int e = i * 128 + tid;
        int r = e >> 4, c = (e & 15) << 2;
        cpa16(&sK0[r * SK_ST + c], &Kg[(size_t)r * DK + c]);
        cpa16(&sV0[r * SV_ST + c], &Vg[(size_t)r * DK + c]);
    }
    cpa_commit();

    // stage Q: pre-rounded; x0.125 is an exact exponent shift so still tf32
#pragma unroll
    for (int i = 0; i < 16; i++) {
        int e = i * 128 + tid;
        int r = e >> 4, c = (e & 15) << 2;
        float4 v = *(const float4*)&Qg[(size_t)(qb * 128 + r) * DK + c];
        float4 o;
        o.x = v.x * 0.125f; o.y = v.y * 0.125f;
        o.z = v.z * 0.125f; o.w = v.w * 0.125f;
        *(float4*)&sQP[r * SQ_ST + c] = o;
    }
    __syncthreads();

    // hoist Q fragments: 2 m-tiles x 8 k-steps x 4 regs
    unsigned qf[2][8][4];
#pragma unroll
    for (int mt = 0; mt < 2; mt++) {
        const int qr = w * 32 + mt * 16 + g;
#pragma unroll
        for (int ks = 0; ks < 8; ks++) {
            const float* p = &sQP[qr * SQ_ST + ks * 8 + t];
            qf[mt][ks][0] = __float_as_uint(p[0]);
            qf[mt][ks][1] = __float_as_uint(p[8 * SQ_ST]);
            qf[mt][ks][2] = __float_as_uint(p[4]);
            qf[mt][ks][3] = __float_as_uint(p[8 * SQ_ST + 4]);
        }
    }

    float mrun[2][2] = {{-1e30f, -1e30f}, {-1e30f, -1e30f}};
    float lrun[2][2] = {{0.f, 0.f}, {0.f, 0.f}};
    float oacc[2][8][4];
#pragma unroll
    for (int mt = 0; mt < 2; mt++)
#pragma unroll
        for (int nt = 0; nt < 8; nt++)
#pragma unroll
            for (int k = 0; k < 4; k++) oacc[mt][nt][k] = 0.f;

    for (int kb = 0; kb <= kb_max; kb++) {
        __syncthreads();   // buffer (kb+1)&1 free; Q->qf hoist done (kb=0)
        if (kb < kb_max) {
            float* sK = sK0 + ((kb + 1) & 1) * SK_BUF;
            float* sV = sV0 + ((kb + 1) & 1) * SV_BUF;
#pragma unroll
            for (int i = 0; i < 8; i++) {
                int e = i * 128 + tid;
                int r = e >> 4, c = (e & 15) << 2;
                cpa16(&sK[r * SK_ST + c], &Kg[(size_t)((kb + 1) * 64 + r) * DK + c]);
                cpa16(&sV[r * SV_ST + c], &Vg[(size_t)((kb + 1) * 64 + r) * DK + c]);
            }
        }
        cpa_commit();
        cpa_wait<1>();
        __syncthreads();

        const float* sK = sK0 + (kb & 1) * SK_BUF;
        const float* sV = sV0 + (kb & 1) * SV_BUF;

        // S = Q K^T : batch kf loads per k-step, then mma
        float s[2][8][4];
#pragma unroll
        for (int mt = 0; mt < 2; mt++)
#pragma unroll
            for (int nt = 0; nt < 8; nt++)
#pragma unroll
                for (int k = 0; k < 4; k++) s[mt][nt][k] = 0.f;

#pragma unroll
        for (int ks = 0; ks < 8; ks++) {
            unsigned kf[8][2];
#pragma unroll
            for (int nt = 0; nt < 8; nt++) {
                const float* p = &sK[(nt * 8 + g) * SK_ST + ks * 8 + t];
                kf[nt][0] = __float_as_uint(p[0]);
                kf[nt][1] = __float_as_uint(p[4]);
            }
#pragma unroll
            for (int nt = 0; nt < 8; nt++) {
                mma8(s[0][nt], qf[0][ks], kf[nt]);
                mma8(s[1][nt], qf[1][ks], kf[nt]);
            }
        }

        // causal mask (only the last two kv-blocks intersect the diagonal)
        if (kb >= 2 * qb) {
#pragma unroll
            for (int mt = 0; mt < 2; mt++) {
                int qg = qb * 128 + w * 32 + mt * 16 + g;
#pragma unroll
                for (int nt = 0; nt < 8; nt++) {
                    int col = kb * 64 + nt * 8 + 2 * t;
                    if (col     > qg)     s[mt][nt][0] = -1e30f;
                    if (col + 1 > qg)     s[mt][nt][1] = -1e30f;
                    if (col     > qg + 8) s[mt][nt][2] = -1e30f;
                    if (col + 1 > qg + 8) s[mt][nt][3] = -1e30f;
                }
            }
        }

        __syncwarp();   // this warp's prior PV reads of its P rows done

        // online softmax per m-tile, per row-half
#pragma unroll
        for (int mt = 0; mt < 2; mt++) {
            const int qr = w * 32 + mt * 16 + g;
#pragma unroll
            for (int r = 0; r < 2; r++) {
                float mx = -1e30f;
#pragma unroll
                for (int nt = 0; nt < 8; nt++)
                    mx = fmaxf(mx, fmaxf(s[mt][nt][2*r], s[mt][nt][2*r + 1]));
                mx = fmaxf(mx, __shfl_xor_sync(0xffffffffu, mx, 1));
                mx = fmaxf(mx, __shfl_xor_sync(0xffffffffu, mx, 2));
                float mnew = fmaxf(mrun[mt][r], mx);
                float corr = __expf(mrun[mt][r] - mnew);
                float rs = 0.f;
                float* prow = &sQP[(qr + 8 * r) * SQ_ST];
#pragma unroll
                for (int nt = 0; nt < 8; nt++) {
                    float p0 = __expf(s[mt][nt][2*r]     - mnew);
                    float p1 = __expf(s[mt][nt][2*r + 1] - mnew);
                    rs += p0 + p1;
                    *(float2*)&prow[nt * 8 + 2 * t] = make_float2(f2tff(p0), f2tff(p1));
                }
                rs += __shfl_xor_sync(0xffffffffu, rs, 1);
                rs += __shfl_xor_sync(0xffffffffu, rs, 2);
                lrun[mt][r] = lrun[mt][r] * corr + rs;
                mrun[mt][r] = mnew;
#pragma unroll
                for (int nt = 0; nt < 8; nt++) {
                    oacc[mt][nt][2*r]     *= corr;
                    oacc[mt][nt][2*r + 1] *= corr;
                }
            }
        }
        __syncwarp();

        // O += P V : batch vf loads per k-step, then mma
#pragma unroll
        for (int ks = 0; ks < 8; ks++) {
            unsigned pf[2][4];
#pragma unroll
            for (int mt = 0; mt < 2; mt++) {
                const float* pp = &sQP[(w * 32 + mt * 16 + g) * SQ_ST + ks * 8 + t];
                pf[mt][0] = __float_as_uint(pp[0]);
                pf[mt][1] = __float_as_uint(pp[8 * SQ_ST]);
                pf[mt][2] = __float_as_uint(pp[4]);
                pf[mt][3] = __float_as_uint(pp[8 * SQ_ST + 4]);
            }
            unsigned vf[8][2];
#pragma unroll
            for (int nt = 0; nt < 8; nt++) {
                const float* vp = &sV[(ks * 8 + t) * SV_ST + nt * 8 + g];
                vf[nt][0] = __float_as_uint(vp[0]);
                vf[nt][1] = __float_as_uint(vp[4 * SV_ST]);
            }
#pragma unroll
            for (int nt = 0; nt < 8; nt++) {
                mma8(oacc[0][nt], pf[0], vf[nt]);
                mma8(oacc[1][nt], pf[1], vf[nt]);
            }
        }
    }

    // epilogue: normalize, round to tf32, scatter to [B,S,D]
    const int b = bh >> 4;
    const int h = bh & 15;
#pragma unroll
    for (int mt = 0; mt < 2; mt++) {
#pragma unroll
        for (int r = 0; r < 2; r++) {
            float inv = 1.f / lrun[mt][r];
            int q = qb * 128 + w * 32 + mt * 16 + g + 8 * r;
            float* dst = &g_O[((size_t)b * SSZ + q) * DSZ + h * DK];
#pragma unroll
            for (int nt = 0; nt < 8; nt++)
                *(float2*)&dst[nt * 8 + 2 * t] =
                    make_float2(f2tff(oacc[mt][nt][2*r] * inv),
                                f2tff(oacc[mt][nt][2*r + 1] * inv));
        }
    }
}

// ---------------------------------------------------------------------------
extern "C" void kernel_launch(void* const* d_in, const int* in_sizes, int n_in,
                              void* d_out, int out_size) {
    (void)in_sizes; (void)n_in; (void)out_size;
    const float* x  = (const float*)d_in[0];
    const float* Wq = (const float*)d_in[1];
    const float* Wk = (const float*)d_in[2];
    const float* Wv = (const float*)d_in[3];
    const float* Wo = (const float*)d_in[4];
    float* out = (float*)d_out;

    const int gemm_smem = 2 * GSTG * GBUF * (int)sizeof(float);  // 110592 B
    cudaFuncSetAttribute(gemm_qkv_kernel, cudaFuncAttributeMaxDynamicSharedMemorySize, gemm_smem);
    cudaFuncSetAttribute(gemm_out_kernel, cudaFuncAttributeMaxDynamicSharedMemorySize, gemm_smem);
    const int attn_smem = (128*SQ_ST + 2*SK_BUF + 2*SV_BUF) * (int)sizeof(float);  // 110592 B
    cudaFuncSetAttribute(attn_kernel, cudaFuncAttributeMaxDynamicSharedMemorySize, attn_smem);

    rope_table_kernel<<<(SSZ * NPAIR + 255) / 256, 256>>>();

    const int NTOT4 = NX4 + 4 * NW4;
    tf32_round_all_kernel<<<(NTOT4 + 255)/256, 256>>>(
        (const float4*)x, (const float4*)Wq, (const float4*)Wk,
        (const float4*)Wv, (const float4*)Wo);

    gemm_qkv_kernel<<<dim3(8, 32, 3), 128, gemm_smem>>>();
    attn_kernel<<<dim3(SSZ / 128, BSZ * HN), 128, attn_smem>>>();
    gemm_out_kernel<<<dim3(8, 32), 128, gemm_smem>>>(out);
}